// round 9
// baseline (speedup 1.0000x reference)
#include <cuda_runtime.h>
#include <cuda_pipeline.h>

#define Bx 4
#define Nn 2048
#define Dd 512
#define Hh 8
#define ZCH 64     // z chunks
#define ZR  32     // rows per z chunk

// ---------------- device scratch ----------------
__device__ float g_u[Hh][Dd];
__device__ float g_ch[Hh];
__device__ float g_s0p[Hh][8];
__device__ float g_sc[Bx][Hh][Nn];         // node scores
__device__ float g_nm[Bx][Hh];             // softmax max
__device__ float g_nrs[Bx][Hh];            // softmax 1/sum
__device__ float g_p0[Bx][Hh];             // CLS probability
__device__ float g_zp[ZCH][Bx][Hh][Dd];    // p-weighted z partials
__device__ float g_w[Bx][Dd];
__device__ float g_y[Bx][Dd];
__device__ unsigned g_c_sc[Bx] = {0, 0, 0, 0};   // monotonic tail tickets
__device__ unsigned g_c_wo = 0;

__device__ __forceinline__ float warp_sum(float v) {
    #pragma unroll
    for (int o = 16; o; o >>= 1) v += __shfl_xor_sync(0xffffffffu, v, o);
    return v;
}
__device__ __forceinline__ float warp_max(float v) {
    #pragma unroll
    for (int o = 16; o; o >>= 1) v = fmaxf(v, __shfl_xor_sync(0xffffffffu, v, o));
    return v;
}
__device__ __forceinline__ float dot4(float4 a, float4 b) {
    return a.x * b.x + a.y * b.y + a.z * b.z + a.w * b.w;
}

// ============ k_prep: per (head, d-chunk): q0 slice, u, s0 partials, ch ============
// grid (Hh, 8), 512 threads
__global__ void k_prep(const float* __restrict__ Wq, const float* __restrict__ bq,
                       const float* __restrict__ Wk, const float* __restrict__ bk,
                       const float* __restrict__ ct) {
    const int h = blockIdx.x, dc = blockIdx.y;
    const int t = threadIdx.x, wid = t >> 5, lane = t & 31;
    __shared__ __align__(16) float cts[Dd];
    __shared__ float q0s[64], red8[8][64], red64[64];
    cts[t] = ct[t];
    __syncthreads();
    {   // q0 slice for head h: 16 warps x 4 rows
        const float4* cv = (const float4*)cts;
        #pragma unroll
        for (int rr = 0; rr < 4; rr++) {
            const int i = wid + rr * 16;
            const float4* row = (const float4*)(Wq + (size_t)(h * 64 + i) * Dd);
            float s = 0.f;
            #pragma unroll
            for (int k = 0; k < 4; k++) s += dot4(row[lane + 32 * k], cv[lane + 32 * k]);
            s = warp_sum(s);
            if (lane == 0) q0s[i] = s + bq[h * 64 + i];
        }
    }
    __syncthreads();
    const int part8 = t >> 6, dl = t & 63;
    {
        const float* base = Wk + (size_t)(h * 64 + part8 * 8) * Dd + dc * 64 + dl;
        float acc = 0.f;
        #pragma unroll
        for (int i = 0; i < 8; i++) acc += q0s[part8 * 8 + i] * base[(size_t)i * Dd];
        red8[part8][dl] = acc;
    }
    __syncthreads();
    if (t < 64) {
        float u = 0.f;
        #pragma unroll
        for (int p = 0; p < 8; p++) u += red8[p][t];
        g_u[h][dc * 64 + t] = u;
        red64[t] = u * cts[dc * 64 + t];
    }
    __syncthreads();
    if (t < 32) {
        float v = red64[t] + red64[t + 32];
        v = warp_sum(v);
        if (t == 0) g_s0p[h][dc] = v;
        if (dc == 0) {
            float cvv = q0s[t] * bk[h * 64 + t] + q0s[t + 32] * bk[h * 64 + t + 32];
            cvv = warp_sum(cvv);
            if (t == 0) g_ch[h] = cvv;
        }
    }
}

// ============ k_scores: PDL; warp = 2 rows; per-b last block does softmax stats ============
// grid (Nn/16, Bx), 256 threads
__global__ void k_scores(const float* __restrict__ nf, const float* __restrict__ masks) {
    __shared__ __align__(16) float4 us4[Hh * 128];   // 16 KB
    __shared__ float chs[Hh];
    __shared__ unsigned s_old;
    const int b = blockIdx.y;
    const int t = threadIdx.x, wid = t >> 5, lane = t & 31;

    // ---- prolog (independent of k_prep): node rows into registers ----
    const int n0 = blockIdx.x * 16 + wid * 2;
    const float4* x4 = (const float4*)(nf + ((size_t)b * Nn + n0) * Dd);
    float4 xr0[4], xr1[4];
    #pragma unroll
    for (int k = 0; k < 4; k++) { xr0[k] = x4[lane + 32 * k]; xr1[k] = x4[128 + lane + 32 * k]; }
    const float mv0 = masks[(size_t)b * Nn + n0];
    const float mv1 = masks[(size_t)b * Nn + n0 + 1];

    cudaGridDependencySynchronize();   // wait for k_prep results

    {
        const float4* uf = (const float4*)&g_u[0][0];
        #pragma unroll
        for (int k = 0; k < 4; k++) us4[t + k * 256] = uf[t + k * 256];
        if (t < Hh) chs[t] = g_ch[t];
    }
    __syncthreads();
    #pragma unroll
    for (int h = 0; h < Hh; h++) {
        float s0 = 0.f, s1 = 0.f;
        #pragma unroll
        for (int k = 0; k < 4; k++) {
            const float4 uv = us4[h * 128 + lane + 32 * k];
            s0 += dot4(uv, xr0[k]);
            s1 += dot4(uv, xr1[k]);
        }
        s0 = warp_sum(s0);
        s1 = warp_sum(s1);
        if (lane == 0) {
            float v0 = (s0 + chs[h]) * 0.125f;
            float v1 = (s1 + chs[h]) * 0.125f;
            if (mv0 * mv0 == 0.f) v0 = -1e9f;
            if (mv1 * mv1 == 0.f) v1 = -1e9f;
            g_sc[b][h][n0] = v0;
            g_sc[b][h][n0 + 1] = v1;
        }
    }
    cudaTriggerProgrammaticLaunchCompletion();   // let k_z start prefetching

    // ---- per-b last-block softmax stats tail ----
    __threadfence();
    __syncthreads();
    if (t == 0) s_old = atomicAdd(&g_c_sc[b], 1u);
    __syncthreads();
    if ((s_old % (unsigned)gridDim.x) != (unsigned)(gridDim.x - 1)) return;
    __threadfence();
    // warp h handles head h: 2048 scores, 64 per lane
    const int h = wid;
    const float* sp = &g_sc[b][h][0];
    float m = -3e38f;
    #pragma unroll 8
    for (int i = 0; i < 64; i++) m = fmaxf(m, sp[i * 32 + lane]);
    float s0t = 0.f;
    #pragma unroll
    for (int dc = 0; dc < 8; dc++) s0t += g_s0p[h][dc];
    const float s0 = (s0t + g_ch[h]) * 0.125f;
    const float M = fmaxf(warp_max(m), s0);
    float e = 0.f;
    #pragma unroll 8
    for (int i = 0; i < 64; i++) e += expf(sp[i * 32 + lane] - M);
    e = warp_sum(e);
    if (lane == 0) {
        const float S = e + expf(s0 - M);
        g_nm[b][h] = M;
        g_nrs[b][h] = 1.f / S;
        g_p0[b][h] = expf(s0 - M) / S;
    }
}

// ============ k_z: PDL; prefetch nf tile to smem pre-sync; p-weighted partials ============
// grid (ZCH, Bx), 256 threads, 64 KB dyn smem
__global__ void k_z(const float* __restrict__ nf) {
    extern __shared__ __align__(16) float xs[];      // [ZR][Dd] = 64 KB = 4096 float4
    __shared__ float ps[Hh][ZR];
    const int c = blockIdx.x, b = blockIdx.y;
    const int t = threadIdx.x;

    // ---- prolog: cp.async the 32x512 tile (4096 float4, 16 iters x 256 thr) ----
    {
        const float4* src = (const float4*)(nf + ((size_t)b * Nn + c * ZR) * Dd);
        float4* dst = (float4*)xs;
        #pragma unroll
        for (int k = 0; k < 16; k++)
            __pipeline_memcpy_async(&dst[t + k * 256], &src[t + k * 256], 16);
        __pipeline_commit();
    }
    cudaGridDependencySynchronize();   // wait for scores + softmax stats
    {
        const int h = t >> 5, jj = t & 31;
        ps[h][jj] = expf(g_sc[b][h][c * ZR + jj] - g_nm[b][h]) * g_nrs[b][h];
    }
    __pipeline_wait_prior(0);
    __syncthreads();

    float2 acc[Hh];
    #pragma unroll
    for (int h = 0; h < Hh; h++) acc[h] = make_float2(0.f, 0.f);
    const float2* xt = (const float2*)xs;
    #pragma unroll 4
    for (int jj = 0; jj < ZR; jj++) {
        const float2 xv = xt[jj * 256 + t];
        #pragma unroll
        for (int h = 0; h < Hh; h++) {
            const float p = ps[h][jj];
            acc[h].x += p * xv.x;
            acc[h].y += p * xv.y;
        }
    }
    #pragma unroll
    for (int h = 0; h < Hh; h++)
        ((float2*)&g_zp[c][b][h][0])[t] = acc[h];
}

// ============ k_zv: sum chunk partials + CLS term + Wv GEMV ============
// grid (Hh, Bx), 512 threads
__global__ void k_zv(const float* __restrict__ ct, const float* __restrict__ Wv,
                     const float* __restrict__ bv) {
    const int h = blockIdx.x, b = blockIdx.y;
    const int t = threadIdx.x, wid = t >> 5, lane = t & 31;
    __shared__ __align__(16) float zs[Dd];
    {
        float acc = g_p0[b][h] * ct[t];
        #pragma unroll 8
        for (int c = 0; c < ZCH; c++) acc += g_zp[c][b][h][t];
        zs[t] = acc;
    }
    __syncthreads();
    const float4* zv = (const float4*)zs;
    #pragma unroll
    for (int rr = 0; rr < 4; rr++) {
        const int i = h * 64 + wid + rr * 16;
        const float4* row = (const float4*)(Wv + (size_t)i * Dd);
        float s = 0.f;
        #pragma unroll
        for (int k = 0; k < 4; k++) s += dot4(row[lane + 32 * k], zv[lane + 32 * k]);
        s = warp_sum(s);
        if (lane == 0) g_w[b][i] = s + bv[i];
    }
}

// ============ k_wo: PDL; warp = (row, batch); last block does LayerNorm ============
// grid 256, 256 threads
__global__ void k_wo(const float* __restrict__ Wo, const float* __restrict__ bo,
                     const float* __restrict__ ct, const float* __restrict__ gamma,
                     const float* __restrict__ beta, float* __restrict__ out) {
    __shared__ __align__(16) float4 ws4[Bx * 128];   // 8 KB
    __shared__ float red[256];
    __shared__ unsigned s_old;
    const int t = threadIdx.x, wid = t >> 5, lane = t & 31;
    const int gw = blockIdx.x * 8 + wid;
    const int r = gw >> 2, b = gw & 3;

    // ---- prolog: Wo row into registers (independent of k_zv) ----
    const float4* row = (const float4*)(Wo + (size_t)r * Dd);
    float4 rv[4];
    #pragma unroll
    for (int k = 0; k < 4; k++) rv[k] = row[lane + 32 * k];

    cudaGridDependencySynchronize();   // wait for g_w
    {
        const float4* gw4 = (const float4*)&g_w[0][0];
        ws4[t] = gw4[t];
        ws4[t + 256] = gw4[t + 256];
    }
    __syncthreads();
    float s = 0.f;
    #pragma unroll
    for (int k = 0; k < 4; k++) s += dot4(rv[k], ws4[b * 128 + lane + 32 * k]);
    s = warp_sum(s);
    if (lane == 0) g_y[b][r] = s + bo[r] + ct[r];

    // ---- last-block LayerNorm tail ----
    __threadfence();
    __syncthreads();
    if (t == 0) s_old = atomicAdd(&g_c_wo, 1u);
    __syncthreads();
    if ((s_old % (unsigned)gridDim.x) != (unsigned)(gridDim.x - 1)) return;
    __threadfence();
    for (int bb = 0; bb < Bx; bb++) {
        const float y0 = g_y[bb][t], y1 = g_y[bb][t + 256];
        red[t] = y0 + y1;
        __syncthreads();
        for (int o = 128; o; o >>= 1) { if (t < o) red[t] += red[t + o]; __syncthreads(); }
        const float mu = red[0] * (1.f / Dd);
        __syncthreads();
        const float d0 = y0 - mu, d1 = y1 - mu;
        red[t] = d0 * d0 + d1 * d1;
        __syncthreads();
        for (int o = 128; o; o >>= 1) { if (t < o) red[t] += red[t + o]; __syncthreads(); }
        const float rs = rsqrtf(red[0] * (1.f / Dd) + 1e-5f);
        out[(size_t)bb * Dd + t]       = d0 * rs * gamma[t] + beta[t];
        out[(size_t)bb * Dd + t + 256] = d1 * rs * gamma[t + 256] + beta[t + 256];
        __syncthreads();
    }
}

// ---------------- launcher ----------------
static void launch_pdl(void* fn, dim3 grid, dim3 block, void** args, size_t smem) {
    cudaLaunchConfig_t cfg = {};
    cfg.gridDim = grid;
    cfg.blockDim = block;
    cfg.dynamicSmemBytes = smem;
    cfg.stream = 0;
    cudaLaunchAttribute attr[1];
    attr[0].id = cudaLaunchAttributeProgrammaticStreamSerialization;
    attr[0].val.programmaticStreamSerializationAllowed = 1;
    cfg.attrs = attr;
    cfg.numAttrs = 1;
    cudaLaunchKernelExC(&cfg, fn, args);
}

extern "C" void kernel_launch(void* const* d_in, const int* in_sizes, int n_in,
                              void* d_out, int out_size) {
    const float* nf    = (const float*)d_in[0];
    // d_in[1] edge_weights, d_in[2] adj_matrix: dead for CLS-row output
    const float* masks = (const float*)d_in[3];
    const float* ct    = (const float*)d_in[4];
    const float* Wq    = (const float*)d_in[5];
    const float* bq    = (const float*)d_in[6];
    const float* Wk    = (const float*)d_in[7];
    const float* bk    = (const float*)d_in[8];
    const float* Wv    = (const float*)d_in[9];
    const float* bv    = (const float*)d_in[10];
    const float* Wo    = (const float*)d_in[11];
    const float* bo    = (const float*)d_in[12];
    const float* gamma = (const float*)d_in[13];
    const float* beta  = (const float*)d_in[14];
    float* out = (float*)d_out;

    const size_t zsmem = (size_t)ZR * Dd * sizeof(float);   // 64 KB
    static bool attr_set = false;
    if (!attr_set) {
        cudaFuncSetAttribute(k_z, cudaFuncAttributeMaxDynamicSharedMemorySize, (int)zsmem);
        attr_set = true;
    }

    k_prep<<<dim3(Hh, 8), 512>>>(Wq, bq, Wk, bk, ct);

    {   // k_scores with PDL
        void* args[] = { (void*)&nf, (void*)&masks };
        launch_pdl((void*)k_scores, dim3(Nn / 16, Bx), dim3(256), args, 0);
    }
    {   // k_z with PDL + 64 KB smem
        void* args[] = { (void*)&nf };
        launch_pdl((void*)k_z, dim3(ZCH, Bx), dim3(256), args, zsmem);
    }
    k_zv<<<dim3(Hh, Bx), 512>>>(ct, Wv, bv);
    {   // k_wo with PDL (+ LN tail)
        void* args[] = { (void*)&Wo, (void*)&bo, (void*)&ct,
                         (void*)&gamma, (void*)&beta, (void*)&out };
        launch_pdl((void*)k_wo, dim3(256), dim3(256), args, 0);
    }
}